// round 14
// baseline (speedup 1.0000x reference)
#include <cuda_runtime.h>
#include <cstdint>

// Problem dims
#define G1 512
#define E_EDGES 16384
#define S1 8192
#define S2 8192
#define BT 128
#define MAXE 256   // per-t0 edge capacity (lambda=32; generous headroom)

// -------- device scratch --------
__device__ float g_xperm[256 * S1];        //  8MB: x, tf32-rounded, K-cols permuted per 16-block
__device__ float g_vperm[E_EDGES * 256];   // 16MB: v, tf32-rounded, fragment-consumption order

// -------- fused preprocessing --------
// blocks [0,512): xperm. blocks [512, 512+4096): vperm (4 edges/block, smem transpose).
__global__ __launch_bounds__(256) void prep_kernel(const float* __restrict__ x,
                                                   const float* __restrict__ values) {
    if (blockIdx.x < 512) {
        // x: tf32 round + col' = (c%4)*4 + c/4 permute per 16-block
        const size_t blk = (size_t)blockIdx.x * 256 + threadIdx.x;
        const float4* src = reinterpret_cast<const float4*>(x + blk * 16);
        float4 a = __ldg(src + 0), b = __ldg(src + 1), c = __ldg(src + 2), d = __ldg(src + 3);
        float v[16] = {a.x,a.y,a.z,a.w, b.x,b.y,b.z,b.w, c.x,c.y,c.z,c.w, d.x,d.y,d.z,d.w};
        uint32_t t[16];
        #pragma unroll
        for (int i = 0; i < 16; i++)
            asm("cvt.rna.tf32.f32 %0, %1;" : "=r"(t[i]) : "f"(v[i]));
        float4* dst = reinterpret_cast<float4*>(g_xperm + blk * 16);
        #pragma unroll
        for (int g = 0; g < 4; g++)
            dst[g] = make_float4(__uint_as_float(t[g]),     __uint_as_float(t[g + 4]),
                                 __uint_as_float(t[g + 8]), __uint_as_float(t[g + 12]));
    } else {
        // v: tf32 round + fragment-order permute, fully coalesced via smem transpose.
        // Within each 256-block: s = q<<6 | tig<<4 | h<<3 | gid  ->  o = gid<<5 | tig<<3 | h<<2 | q
        __shared__ float sm[1024];
        const int blk = blockIdx.x - 512;              // 0..4095, 4 edges each
        const size_t base = (size_t)blk * 1024;
        const int t = threadIdx.x;
        const float4 in = __ldg(reinterpret_cast<const float4*>(values + base) + t);
        const float iv[4] = {in.x, in.y, in.z, in.w};
        #pragma unroll
        for (int m = 0; m < 4; m++) {
            uint32_t cv;
            asm("cvt.rna.tf32.f32 %0, %1;" : "=r"(cv) : "f"(iv[m]));
            const int f   = t * 4 + m;       // flat source index within 4 edges
            const int el  = f >> 8;          // edge-local 0..3
            const int s   = f & 255;
            const int gid = s & 7;
            const int h   = (s >> 3) & 1;
            const int tig = (s >> 4) & 3;
            const int q   = (s >> 6) & 3;
            const int o   = (gid << 5) | (tig << 3) | (h << 2) | q;
            sm[(el << 8) | o] = __uint_as_float(cv);
        }
        __syncthreads();
        reinterpret_cast<float4*>(g_vperm + base)[t] =
            *reinterpret_cast<const float4*>(&sm[t * 4]);
    }
}

// -------- helpers --------
__device__ __forceinline__ void mma8(float* c,
                                     uint32_t a0, uint32_t a1, uint32_t a2, uint32_t a3,
                                     uint32_t b0, uint32_t b1) {
    asm volatile(
        "mma.sync.aligned.m16n8k8.row.col.f32.tf32.tf32.f32 "
        "{%0,%1,%2,%3}, {%4,%5,%6,%7}, {%8,%9}, {%0,%1,%2,%3};"
        : "+f"(c[0]), "+f"(c[1]), "+f"(c[2]), "+f"(c[3])
        : "r"(a0), "r"(a1), "r"(a2), "r"(a3), "r"(b0), "r"(b1));
}

union F4U { float4 f; uint32_t u[4]; };

// -------- main tensor SpMM: self-bucketing + warp-autonomous register pipeline --------
// grid (512 t0, 2 batch halves), 128 threads = 4 warps; warp w owns batch rows 32w..32w+31.
// Per lane per edge: 4x LDG.128 (A, permuted x) + 2x LDG.128 (B, pre-permuted tf32 v).
__global__ __launch_bounds__(128, 5) void spmm_mma(
    const float* __restrict__ bias,
    const int*   __restrict__ ei,
    float* __restrict__ out)
{
    __shared__ int s_xoff[MAXE];   // t1 * 16  (x column offset, floats)
    __shared__ int s_voff[MAXE];   // e  * 256 (vperm offset, floats)
    __shared__ int s_cnt;

    const int tid  = threadIdx.x;
    const int lane = tid & 31;
    const int wid  = tid >> 5;
    const int gid  = lane >> 2;
    const int tig  = lane & 3;
    const int t0    = blockIdx.x;
    const int bbase = blockIdx.y * BT;

    // ---- self-bucket: scan edge_index for matches on t0, store pre-decoded offsets ----
    if (tid == 0) s_cnt = 0;
    __syncthreads();
    {
        const int4* ei4 = reinterpret_cast<const int4*>(ei);
        #pragma unroll 4
        for (int i = tid; i < E_EDGES / 4; i += 128) {
            const int4 q = __ldg(&ei4[i]);
            const int base = i << 2;
            if (q.x == t0) { int p = atomicAdd(&s_cnt, 1); if (p < MAXE) { s_xoff[p] = __ldg(ei + E_EDGES + base    ) << 4; s_voff[p] = (base    ) << 8; } }
            if (q.y == t0) { int p = atomicAdd(&s_cnt, 1); if (p < MAXE) { s_xoff[p] = __ldg(ei + E_EDGES + base + 1) << 4; s_voff[p] = (base + 1) << 8; } }
            if (q.z == t0) { int p = atomicAdd(&s_cnt, 1); if (p < MAXE) { s_xoff[p] = __ldg(ei + E_EDGES + base + 2) << 4; s_voff[p] = (base + 2) << 8; } }
            if (q.w == t0) { int p = atomicAdd(&s_cnt, 1); if (p < MAXE) { s_xoff[p] = __ldg(ei + E_EDGES + base + 3) << 4; s_voff[p] = (base + 3) << 8; } }
        }
    }
    __syncthreads();
    int n = s_cnt;
    if (n > MAXE) n = MAXE;

    // this lane's A source rows: (bbase + 32*wid + gid) + {0, 8, 16, 24}
    const float* xrow = g_xperm + (size_t)(bbase + (wid << 5) + gid) * S1 + (tig << 2);
    const float* vbase = g_vperm + (lane << 3);

    float acc[2][2][4];
    #pragma unroll
    for (int a = 0; a < 2; a++)
        #pragma unroll
        for (int b = 0; b < 2; b++)
            #pragma unroll
            for (int q = 0; q < 4; q++) acc[a][b][q] = 0.0f;

    F4U xf[2][4];   // 2-slot pipeline of A fragments
    F4U vf[2][2];   // 2-slot pipeline of B fragments (pre-converted tf32 bits)

    auto issue = [&](int k, int s) {
        if (k < n) {
            const float* xp = xrow + s_xoff[k];
            xf[s][0].f = __ldg(reinterpret_cast<const float4*>(xp));
            xf[s][1].f = __ldg(reinterpret_cast<const float4*>(xp +  8 * S1));
            xf[s][2].f = __ldg(reinterpret_cast<const float4*>(xp + 16 * S1));
            xf[s][3].f = __ldg(reinterpret_cast<const float4*>(xp + 24 * S1));
            const float* vp = vbase + s_voff[k];
            vf[s][0].f = __ldg(reinterpret_cast<const float4*>(vp));
            vf[s][1].f = __ldg(reinterpret_cast<const float4*>(vp + 4));
        }
    };

    issue(0, 0);
    issue(1, 1);

    for (int k = 0; k < n; k++) {
        const int s = k & 1;

        // consume slot s in place (no local copies -> lower register pressure)
        mma8(acc[0][0], xf[s][0].u[0], xf[s][1].u[0], xf[s][0].u[1], xf[s][1].u[1], vf[s][0].u[0], vf[s][0].u[1]);
        mma8(acc[0][0], xf[s][0].u[2], xf[s][1].u[2], xf[s][0].u[3], xf[s][1].u[3], vf[s][0].u[2], vf[s][0].u[3]);
        mma8(acc[0][1], xf[s][0].u[0], xf[s][1].u[0], xf[s][0].u[1], xf[s][1].u[1], vf[s][1].u[0], vf[s][1].u[1]);
        mma8(acc[0][1], xf[s][0].u[2], xf[s][1].u[2], xf[s][0].u[3], xf[s][1].u[3], vf[s][1].u[2], vf[s][1].u[3]);
        mma8(acc[1][0], xf[s][2].u[0], xf[s][3].u[0], xf[s][2].u[1], xf[s][3].u[1], vf[s][0].u[0], vf[s][0].u[1]);
        mma8(acc[1][0], xf[s][2].u[2], xf[s][3].u[2], xf[s][2].u[3], xf[s][3].u[3], vf[s][0].u[2], vf[s][0].u[3]);
        mma8(acc[1][1], xf[s][2].u[0], xf[s][3].u[0], xf[s][2].u[1], xf[s][3].u[1], vf[s][1].u[0], vf[s][1].u[1]);
        mma8(acc[1][1], xf[s][2].u[2], xf[s][3].u[2], xf[s][2].u[3], xf[s][3].u[3], vf[s][1].u[2], vf[s][1].u[3]);

        // refill slot s for edge k+2 (WAR on xf/vf regs enforced by scoreboard)
        issue(k + 2, s);
    }

    // ---- epilogue: bias + float2 stores (n == 0 -> pure bias) ----
    #pragma unroll
    for (int t = 0; t < 2; t++) {
        const int row = bbase + (wid << 5) + (t << 4) + gid;
        #pragma unroll
        for (int nt = 0; nt < 2; nt++) {
            const int col = t0 * 16 + (nt << 3) + (tig << 1);
            const float2 bv = __ldg(reinterpret_cast<const float2*>(bias + col));
            float2 o0 = make_float2(acc[t][nt][0] + bv.x, acc[t][nt][1] + bv.y);
            float2 o1 = make_float2(acc[t][nt][2] + bv.x, acc[t][nt][3] + bv.y);
            *reinterpret_cast<float2*>(out + (size_t)row * S2 + col)       = o0;
            *reinterpret_cast<float2*>(out + (size_t)(row + 8) * S2 + col) = o1;
        }
    }
}

// -------- launch: exactly 2 kernels --------
extern "C" void kernel_launch(void* const* d_in, const int* in_sizes, int n_in,
                              void* d_out, int out_size) {
    const float* x      = (const float*)d_in[0];   // (256, 8192)
    const float* values = (const float*)d_in[1];   // (4194304,)
    const float* bias   = (const float*)d_in[2];   // (8192,)
    const int*   eidx   = (const int*)d_in[3];     // (2, 16384)
    float* out = (float*)d_out;                    // (256, 8192)

    prep_kernel<<<512 + E_EDGES / 4, 256>>>(x, values);
    dim3 grid(G1, 2);
    spmm_mma<<<grid, 128>>>(bias, eidx, out);
}

// round 15
// speedup vs baseline: 1.9279x; 1.9279x over previous
#include <cuda_runtime.h>
#include <cstdint>

// Problem dims
#define G1 512
#define E_EDGES 16384
#define S1 8192
#define S2 8192
#define BT 128
#define MAXE 256   // per-t0 edge capacity (lambda=32; generous headroom)

// -------- device scratch --------
__device__ float g_xperm[256 * S1];        //  8MB: x, tf32-rounded, K-cols permuted per 16-block
__device__ float g_vperm[E_EDGES * 256];   // 16MB: v, tf32-rounded, fragment-consumption order

// -------- fused preprocessing --------
// blocks [0,512): xperm. blocks [512, 512+4096): vperm (4 edges/block, smem transpose).
__global__ __launch_bounds__(256) void prep_kernel(const float* __restrict__ x,
                                                   const float* __restrict__ values) {
    if (blockIdx.x < 512) {
        // x: tf32 round + col' = (c%4)*4 + c/4 permute per 16-block
        const size_t blk = (size_t)blockIdx.x * 256 + threadIdx.x;
        const float4* src = reinterpret_cast<const float4*>(x + blk * 16);
        float4 a = __ldg(src + 0), b = __ldg(src + 1), c = __ldg(src + 2), d = __ldg(src + 3);
        float v[16] = {a.x,a.y,a.z,a.w, b.x,b.y,b.z,b.w, c.x,c.y,c.z,c.w, d.x,d.y,d.z,d.w};
        uint32_t t[16];
        #pragma unroll
        for (int i = 0; i < 16; i++)
            asm("cvt.rna.tf32.f32 %0, %1;" : "=r"(t[i]) : "f"(v[i]));
        float4* dst = reinterpret_cast<float4*>(g_xperm + blk * 16);
        #pragma unroll
        for (int g = 0; g < 4; g++)
            dst[g] = make_float4(__uint_as_float(t[g]),     __uint_as_float(t[g + 4]),
                                 __uint_as_float(t[g + 8]), __uint_as_float(t[g + 12]));
    } else {
        // v: tf32 round + fragment-order permute, fully coalesced via smem transpose.
        // Within each 256-block: s = q<<6 | tig<<4 | h<<3 | gid  ->  o = gid<<5 | tig<<3 | h<<2 | q
        __shared__ float sm[1024];
        const int blk = blockIdx.x - 512;              // 0..4095, 4 edges each
        const size_t base = (size_t)blk * 1024;
        const int t = threadIdx.x;
        const float4 in = __ldg(reinterpret_cast<const float4*>(values + base) + t);
        const float iv[4] = {in.x, in.y, in.z, in.w};
        #pragma unroll
        for (int m = 0; m < 4; m++) {
            uint32_t cv;
            asm("cvt.rna.tf32.f32 %0, %1;" : "=r"(cv) : "f"(iv[m]));
            const int f   = t * 4 + m;       // flat source index within 4 edges
            const int el  = f >> 8;          // edge-local 0..3
            const int s   = f & 255;
            const int gid = s & 7;
            const int h   = (s >> 3) & 1;
            const int tig = (s >> 4) & 3;
            const int q   = (s >> 6) & 3;
            const int o   = (gid << 5) | (tig << 3) | (h << 2) | q;
            sm[(el << 8) | o] = __uint_as_float(cv);
        }
        __syncthreads();
        reinterpret_cast<float4*>(g_vperm + base)[t] =
            *reinterpret_cast<const float4*>(&sm[t * 4]);
    }
}

// -------- helpers --------
__device__ __forceinline__ void mma8(float* c,
                                     uint32_t a0, uint32_t a1, uint32_t a2, uint32_t a3,
                                     uint32_t b0, uint32_t b1) {
    asm volatile(
        "mma.sync.aligned.m16n8k8.row.col.f32.tf32.tf32.f32 "
        "{%0,%1,%2,%3}, {%4,%5,%6,%7}, {%8,%9}, {%0,%1,%2,%3};"
        : "+f"(c[0]), "+f"(c[1]), "+f"(c[2]), "+f"(c[3])
        : "r"(a0), "r"(a1), "r"(a2), "r"(a3), "r"(b0), "r"(b1));
}

union F4U { float4 f; uint32_t u[4]; };

// -------- main tensor SpMM: self-bucketing + warp-autonomous register pipeline --------
// grid (512 t0, 2 batch halves), 128 threads = 4 warps; warp w owns batch rows 32w..32w+31.
// Per lane per edge: 4x LDG.128 (A, permuted x) + 2x LDG.128 (B, pre-permuted tf32 v).
__global__ __launch_bounds__(128) void spmm_mma(
    const float* __restrict__ bias,
    const int*   __restrict__ ei,
    float* __restrict__ out)
{
    __shared__ int s_xoff[MAXE];   // t1 * 16  (x column offset, floats)
    __shared__ int s_voff[MAXE];   // e  * 256 (vperm offset, floats)
    __shared__ int s_cnt;

    const int tid  = threadIdx.x;
    const int lane = tid & 31;
    const int wid  = tid >> 5;
    const int gid  = lane >> 2;
    const int tig  = lane & 3;
    const int t0    = blockIdx.x;
    const int bbase = blockIdx.y * BT;

    // ---- self-bucket: scan edge_index for matches on t0, store pre-decoded offsets ----
    if (tid == 0) s_cnt = 0;
    __syncthreads();
    {
        const int4* ei4 = reinterpret_cast<const int4*>(ei);
        #pragma unroll 4
        for (int i = tid; i < E_EDGES / 4; i += 128) {
            const int4 q = __ldg(&ei4[i]);
            const int base = i << 2;
            if (q.x == t0) { int p = atomicAdd(&s_cnt, 1); if (p < MAXE) { s_xoff[p] = __ldg(ei + E_EDGES + base    ) << 4; s_voff[p] = (base    ) << 8; } }
            if (q.y == t0) { int p = atomicAdd(&s_cnt, 1); if (p < MAXE) { s_xoff[p] = __ldg(ei + E_EDGES + base + 1) << 4; s_voff[p] = (base + 1) << 8; } }
            if (q.z == t0) { int p = atomicAdd(&s_cnt, 1); if (p < MAXE) { s_xoff[p] = __ldg(ei + E_EDGES + base + 2) << 4; s_voff[p] = (base + 2) << 8; } }
            if (q.w == t0) { int p = atomicAdd(&s_cnt, 1); if (p < MAXE) { s_xoff[p] = __ldg(ei + E_EDGES + base + 3) << 4; s_voff[p] = (base + 3) << 8; } }
        }
    }
    __syncthreads();
    int n = s_cnt;
    if (n > MAXE) n = MAXE;

    // this lane's A source rows: (bbase + 32*wid + gid) + {0, 8, 16, 24}
    const float* xrow  = g_xperm + (size_t)(bbase + (wid << 5) + gid) * S1 + (tig << 2);
    const float* vbase = g_vperm + (lane << 3);

    float acc[2][2][4];
    #pragma unroll
    for (int a = 0; a < 2; a++)
        #pragma unroll
        for (int b = 0; b < 2; b++)
            #pragma unroll
            for (int q = 0; q < 4; q++) acc[a][b][q] = 0.0f;

    F4U xf[2][4];   // 2-slot pipeline of A fragments (constant slot indices only)
    F4U vf[2][2];   // 2-slot pipeline of B fragments (pre-converted tf32 bits)

    // issue: loads edge k into COMPILE-TIME slot S (keeps xf/vf in registers)
    #define ISSUE(k, S)                                                            \
        if ((k) < n) {                                                             \
            const float* xp = xrow + s_xoff[(k)];                                  \
            xf[S][0].f = __ldg(reinterpret_cast<const float4*>(xp));               \
            xf[S][1].f = __ldg(reinterpret_cast<const float4*>(xp +  8 * S1));     \
            xf[S][2].f = __ldg(reinterpret_cast<const float4*>(xp + 16 * S1));     \
            xf[S][3].f = __ldg(reinterpret_cast<const float4*>(xp + 24 * S1));     \
            const float* vp = vbase + s_voff[(k)];                                 \
            vf[S][0].f = __ldg(reinterpret_cast<const float4*>(vp));               \
            vf[S][1].f = __ldg(reinterpret_cast<const float4*>(vp + 4));           \
        }

    // consume slot S (copy to locals first: frees slot, enables early refill), then refill
    #define STEP(k, S)                                                             \
        {                                                                          \
            F4U X0 = xf[S][0], X1 = xf[S][1], X2 = xf[S][2], X3 = xf[S][3];        \
            F4U B0 = vf[S][0], B1 = vf[S][1];                                      \
            ISSUE((k) + 2, S);                                                     \
            mma8(acc[0][0], X0.u[0], X1.u[0], X0.u[1], X1.u[1], B0.u[0], B0.u[1]); \
            mma8(acc[0][0], X0.u[2], X1.u[2], X0.u[3], X1.u[3], B0.u[2], B0.u[3]); \
            mma8(acc[0][1], X0.u[0], X1.u[0], X0.u[1], X1.u[1], B1.u[0], B1.u[1]); \
            mma8(acc[0][1], X0.u[2], X1.u[2], X0.u[3], X1.u[3], B1.u[2], B1.u[3]); \
            mma8(acc[1][0], X2.u[0], X3.u[0], X2.u[1], X3.u[1], B0.u[0], B0.u[1]); \
            mma8(acc[1][0], X2.u[2], X3.u[2], X2.u[3], X3.u[3], B0.u[2], B0.u[3]); \
            mma8(acc[1][1], X2.u[0], X3.u[0], X2.u[1], X3.u[1], B1.u[0], B1.u[1]); \
            mma8(acc[1][1], X2.u[2], X3.u[2], X2.u[3], X3.u[3], B1.u[2], B1.u[3]); \
        }

    ISSUE(0, 0);
    ISSUE(1, 1);

    int k = 0;
    for (; k + 1 < n; k += 2) {   // unrolled x2: slot indices are compile-time
        STEP(k, 0);
        STEP(k + 1, 1);
    }
    if (k < n) STEP(k, 0);

    #undef ISSUE
    #undef STEP

    // ---- epilogue: bias + float2 stores (n == 0 -> pure bias) ----
    #pragma unroll
    for (int t = 0; t < 2; t++) {
        const int row = bbase + (wid << 5) + (t << 4) + gid;
        #pragma unroll
        for (int nt = 0; nt < 2; nt++) {
            const int col = t0 * 16 + (nt << 3) + (tig << 1);
            const float2 bv = __ldg(reinterpret_cast<const float2*>(bias + col));
            float2 o0 = make_float2(acc[t][nt][0] + bv.x, acc[t][nt][1] + bv.y);
            float2 o1 = make_float2(acc[t][nt][2] + bv.x, acc[t][nt][3] + bv.y);
            *reinterpret_cast<float2*>(out + (size_t)row * S2 + col)       = o0;
            *reinterpret_cast<float2*>(out + (size_t)(row + 8) * S2 + col) = o1;
        }
    }
}

// -------- launch: exactly 2 kernels --------
extern "C" void kernel_launch(void* const* d_in, const int* in_sizes, int n_in,
                              void* d_out, int out_size) {
    const float* x      = (const float*)d_in[0];   // (256, 8192)
    const float* values = (const float*)d_in[1];   // (4194304,)
    const float* bias   = (const float*)d_in[2];   // (8192,)
    const int*   eidx   = (const int*)d_in[3];     // (2, 16384)
    float* out = (float*)d_out;                    // (256, 8192)

    prep_kernel<<<512 + E_EDGES / 4, 256>>>(x, values);
    dim3 grid(G1, 2);
    spmm_mma<<<grid, 128>>>(bias, eidx, out);
}